// round 12
// baseline (speedup 1.0000x reference)
#include <cuda_runtime.h>
#include <math.h>
#include <stdint.h>

// EnhancedFinancialGAT collapse: initial node features are uniform over nodes,
// so GAT attention (softmax weights summing to 1 per dst) aggregates identical
// messages -> each GAT layer == relu(W @ g + b). Whole net = per-item MLP.
//
// R11 -> R12: cluster-8, 4 items per cluster. 32 rows/CTA per shared layer,
// 1 warp per row; each weight float4 feeds 16 FMAs (4 items). Lanes 0-7 fan
// results to the 8 ranks. Tail: rank=(item,branch), 8-way, no cluster syncs.

#define IN_DIM 64
#define ACT_STRIDE 704   // per item: s0[320] | s1[256] | s2[128]
#define NITEMS 4

__device__ __forceinline__ uint32_t smem_u32(const void* p) {
    uint32_t a;
    asm("{ .reg .u64 t; cvta.to.shared.u64 t, %1; cvt.u32.u64 %0, t; }"
        : "=r"(a) : "l"(p));
    return a;
}
__device__ __forceinline__ uint32_t mapa_u32(uint32_t addr, uint32_t rank) {
    uint32_t r;
    asm("mapa.shared::cluster.u32 %0, %1, %2;" : "=r"(r) : "r"(addr), "r"(rank));
    return r;
}
__device__ __forceinline__ void st_peer(uint32_t addr, float v) {
    asm volatile("st.shared::cluster.f32 [%0], %1;" :: "r"(addr), "f"(v) : "memory");
}
__device__ __forceinline__ void cluster_sync() {
    asm volatile("barrier.cluster.arrive.aligned;" ::: "memory");
    asm volatile("barrier.cluster.wait.aligned;" ::: "memory");
}

// Shared layer, one warp per output row, 4 items. NCOL4 = cols/4.
// Lane l covers chunks {l, l+32, ...}. After butterfly, every lane holds all
// 4 item sums; lanes 0..7 store the relu'd outputs to rank==lane.
template<int NCOL4>
__device__ __forceinline__ void shared_layer_c8(
    const float* __restrict__ W, const float* __restrict__ bias,
    const float* __restrict__ act, int in_off, int out_off,
    int row, int lane, const uint32_t* __restrict__ peer)
{
    const float4* __restrict__ w4 = reinterpret_cast<const float4*>(W) + row * NCOL4;
    float s0 = 0.f, s1 = 0.f, s2 = 0.f, s3 = 0.f;
#pragma unroll
    for (int j = lane; j < NCOL4; j += 32) {
        const float4 w = __ldg(w4 + j);
        {
            const float4 u = reinterpret_cast<const float4*>(act + 0 * ACT_STRIDE + in_off)[j];
            s0 = fmaf(w.x, u.x, fmaf(w.y, u.y, fmaf(w.z, u.z, fmaf(w.w, u.w, s0))));
        }
        {
            const float4 u = reinterpret_cast<const float4*>(act + 1 * ACT_STRIDE + in_off)[j];
            s1 = fmaf(w.x, u.x, fmaf(w.y, u.y, fmaf(w.z, u.z, fmaf(w.w, u.w, s1))));
        }
        {
            const float4 u = reinterpret_cast<const float4*>(act + 2 * ACT_STRIDE + in_off)[j];
            s2 = fmaf(w.x, u.x, fmaf(w.y, u.y, fmaf(w.z, u.z, fmaf(w.w, u.w, s2))));
        }
        {
            const float4 u = reinterpret_cast<const float4*>(act + 3 * ACT_STRIDE + in_off)[j];
            s3 = fmaf(w.x, u.x, fmaf(w.y, u.y, fmaf(w.z, u.z, fmaf(w.w, u.w, s3))));
        }
    }
#pragma unroll
    for (int o = 1; o < 32; o <<= 1) {
        s0 += __shfl_xor_sync(0xffffffffu, s0, o);
        s1 += __shfl_xor_sync(0xffffffffu, s1, o);
        s2 += __shfl_xor_sync(0xffffffffu, s2, o);
        s3 += __shfl_xor_sync(0xffffffffu, s3, o);
    }
    const float bs = __ldg(bias + row);
    if (lane < 8) {
        const uint32_t base = peer[lane] + (uint32_t)(out_off + row) * 4;
        st_peer(base + 0 * (ACT_STRIDE * 4), fmaxf(s0 + bs, 0.f));
        st_peer(base + 1 * (ACT_STRIDE * 4), fmaxf(s1 + bs, 0.f));
        st_peer(base + 2 * (ACT_STRIDE * 4), fmaxf(s2 + bs, 0.f));
        st_peer(base + 3 * (ACT_STRIDE * 4), fmaxf(s3 + bs, 0.f));
    }
}

// Local tail layer row (one item), 8 lanes per row.
template<int NCH>
__device__ __forceinline__ void local_layer8(
    const float* __restrict__ W, const float* __restrict__ bias,
    const float* __restrict__ vin, float* __restrict__ vout,
    int row, int l)
{
    const float4* __restrict__ w4 = reinterpret_cast<const float4*>(W) + row * (NCH * 8);
    const float4* __restrict__ u4 = reinterpret_cast<const float4*>(vin);
    float4 w[NCH];
#pragma unroll
    for (int j = 0; j < NCH; j++) w[j] = __ldg(w4 + j * 8 + l);
    float4 p = make_float4(0.f, 0.f, 0.f, 0.f);
#pragma unroll
    for (int j = 0; j < NCH; j++) {
        const float4 u = u4[j * 8 + l];
        p.x = fmaf(w[j].x, u.x, p.x); p.y = fmaf(w[j].y, u.y, p.y);
        p.z = fmaf(w[j].z, u.z, p.z); p.w = fmaf(w[j].w, u.w, p.w);
    }
    float r = (p.x + p.y) + (p.z + p.w);
#pragma unroll
    for (int o = 1; o < 8; o <<= 1) r += __shfl_xor_sync(0xffffffffu, r, o);
    if (l == 0) vout[row] = fmaxf(r + __ldg(bias + row), 0.f);
}

__global__ __launch_bounds__(1024) __cluster_dims__(8, 1, 1)
void gat_c8_kernel(
    const float* __restrict__ x, const int* __restrict__ company_idx,
    const float* __restrict__ W_in,  const float* __restrict__ b_in,
    const float* __restrict__ gat_W, const float* __restrict__ gat_b,
    const float* __restrict__ emb,
    const float* __restrict__ W_fuse, const float* __restrict__ b_fuse,
    const float* __restrict__ W_p1, const float* __restrict__ b_p1,
    const float* __restrict__ W_p2, const float* __restrict__ b_p2,
    const float* __restrict__ W_p3, const float* __restrict__ b_p3,
    const float* __restrict__ W_d1, const float* __restrict__ b_d1,
    const float* __restrict__ W_d2, const float* __restrict__ b_d2,
    const float* __restrict__ W_d3, const float* __restrict__ b_d3,
    float* __restrict__ out)
{
    __shared__ __align__(16) float act[NITEMS * ACT_STRIDE];

    const int tid  = threadIdx.x;
    const int warp = tid >> 5;        // 0..31 = row within this CTA's slice
    const int lane = tid & 31;
    uint32_t rank;
    asm("mov.u32 %0, %%cluster_ctarank;" : "=r"(rank));
    const int b0   = (blockIdx.x >> 3) * NITEMS;  // 4 items per 8-CTA cluster
    const int base = rank * 32;                   // rows owned by this CTA

    uint32_t peer[8];
    {
        const uint32_t a = smem_u32(act);
#pragma unroll
        for (int r = 0; r < 8; r++) peer[r] = mapa_u32(a, r);
    }

    // init: x + emb rows for all 4 items (local copies in every CTA)
    if (tid < 64 * NITEMS) {
        const int it = tid >> 6, c = tid & 63;
        const int bb = b0 + it;
        float* s0 = act + it * ACT_STRIDE;
        s0[c]       = __ldg(&x[bb * IN_DIM + c]);
        s0[256 + c] = __ldg(&emb[__ldg(&company_idx[bb]) * IN_DIM + c]);
    }
    __syncthreads();

    // W_in: 256x64, s0[0:64] -> s1
    shared_layer_c8<16>(W_in, b_in, act, 0, 320, base + warp, lane, peer);
    cluster_sync();
    // GAT layers (uniform-node collapse): 256x256
    shared_layer_c8<64>(gat_W,          gat_b,       act, 320, 0,   base + warp, lane, peer);
    cluster_sync();
    shared_layer_c8<64>(gat_W +  65536, gat_b + 256, act, 0,   320, base + warp, lane, peer);
    cluster_sync();
    shared_layer_c8<64>(gat_W + 131072, gat_b + 512, act, 320, 0,   base + warp, lane, peer);
    cluster_sync();
    // fuse: 256x320 (s0 = [gat2 | emb]) -> s1
    shared_layer_c8<80>(W_fuse, b_fuse, act, 0, 320, base + warp, lane, peer);
    cluster_sync();

    // tail: rank -> (item = rank>>1, branch = rank&1), fully local
    const int item   = rank >> 1;
    const int branch = rank & 1;             // 0 = price, 1 = direction
    const float* W1 = branch ? W_d1 : W_p1;
    const float* c1 = branch ? b_d1 : b_p1;
    const float* W2 = branch ? W_d2 : W_p2;
    const float* c2 = branch ? b_d2 : b_p2;
    const float* W3 = branch ? W_d3 : W_p3;
    const float* c3 = branch ? b_d3 : b_p3;
    const float* fused = act + item * ACT_STRIDE + 320;

    const int grp8 = tid >> 3, l8 = tid & 7;
    // l1: 128x256, fused -> act[0:128] (scratch; item0 s0 no longer needed)
    local_layer8<8>(W1, c1, fused, act, grp8, l8);
    __syncthreads();
    // l2: 64x128, act[0:128] -> act[576:640]
    if (grp8 < 64)
        local_layer8<4>(W2, c2, act, act + 576, grp8, l8);
    __syncthreads();

    // head: warp 0, 64-dot
    if (tid < 32) {
        const float2 wv = __ldg(&reinterpret_cast<const float2*>(W3)[tid]);
        const float2 vv = reinterpret_cast<const float2*>(act + 576)[tid];
        float r = fmaf(wv.x, vv.x, wv.y * vv.y);
#pragma unroll
        for (int o = 16; o; o >>= 1) r += __shfl_xor_sync(0xffffffffu, r, o);
        if (tid == 0) {
            const float v = r + __ldg(c3);
            const int bb = b0 + item;
            if (branch == 0) out[bb] = v;                            // price
            else             out[64 + bb] = 1.f / (1.f + expf(-v));  // direction
        }
    }
}

extern "C" void kernel_launch(void* const* d_in, const int* in_sizes, int n_in,
                              void* d_out, int out_size) {
    const float* x      = (const float*)d_in[0];
    const int*   ci     = (const int*)  d_in[1];
    const float* W_in   = (const float*)d_in[4];
    const float* b_in   = (const float*)d_in[5];
    const float* gat_W  = (const float*)d_in[6];
    const float* gat_b  = (const float*)d_in[11];
    const float* emb    = (const float*)d_in[12];
    const float* W_fuse = (const float*)d_in[13];
    const float* b_fuse = (const float*)d_in[14];
    const float* W_p1   = (const float*)d_in[15];
    const float* b_p1   = (const float*)d_in[16];
    const float* W_p2   = (const float*)d_in[17];
    const float* b_p2   = (const float*)d_in[18];
    const float* W_p3   = (const float*)d_in[19];
    const float* b_p3   = (const float*)d_in[20];
    const float* W_d1   = (const float*)d_in[21];
    const float* b_d1   = (const float*)d_in[22];
    const float* W_d2   = (const float*)d_in[23];
    const float* b_d2   = (const float*)d_in[24];
    const float* W_d3   = (const float*)d_in[25];
    const float* b_d3   = (const float*)d_in[26];

    const int B = in_sizes[0] / IN_DIM;  // 64

    // 16 clusters x 8 CTAs = 128 blocks, 4 items per cluster
    gat_c8_kernel<<<(B / NITEMS) * 8, 1024>>>(
        x, ci, W_in, b_in, gat_W, gat_b, emb, W_fuse, b_fuse,
        W_p1, b_p1, W_p2, b_p2, W_p3, b_p3,
        W_d1, b_d1, W_d2, b_d2, W_d3, b_d3,
        (float*)d_out);
}

// round 14
// speedup vs baseline: 1.4237x; 1.4237x over previous
#include <cuda_runtime.h>
#include <math.h>
#include <stdint.h>

// EnhancedFinancialGAT collapse: initial node features are uniform over nodes,
// so GAT attention (softmax weights summing to 1 per dst) aggregates identical
// messages -> each GAT layer == relu(W @ g + b). Whole net = per-item MLP.
//
// R12 -> R13: revert to R11 (cluster-4, 2 items, 16-lane row groups; best =
// 17.1us). Replace the 5 barrier.cluster stage syncs (~500-2000cyc each, full
// 4x1024-thread convergence + L1 flush) with one mbarrier per CTA expecting
// 256 arrivals (64 group-leaders x 4 CTAs): leaders st.shared::cluster their
// row results then mbarrier.arrive.release.cluster on each rank's barrier;
// consumers try_wait.parity.acquire.cluster. Parity alternates per stage.

#define IN_DIM 64
#define ACT_STRIDE 704   // per item: s0[320] | s1[256] | s2[128]

__device__ __forceinline__ uint32_t smem_u32(const void* p) {
    uint32_t a;
    asm("{ .reg .u64 t; cvta.to.shared.u64 t, %1; cvt.u32.u64 %0, t; }"
        : "=r"(a) : "l"(p));
    return a;
}
__device__ __forceinline__ uint32_t mapa_u32(uint32_t addr, uint32_t rank) {
    uint32_t r;
    asm("mapa.shared::cluster.u32 %0, %1, %2;" : "=r"(r) : "r"(addr), "r"(rank));
    return r;
}
__device__ __forceinline__ void st_peer(uint32_t addr, float v) {
    asm volatile("st.shared::cluster.f32 [%0], %1;" :: "r"(addr), "f"(v) : "memory");
}
__device__ __forceinline__ void cluster_sync() {
    asm volatile("barrier.cluster.arrive.aligned;" ::: "memory");
    asm volatile("barrier.cluster.wait.aligned;" ::: "memory");
}
__device__ __forceinline__ void mbar_init(uint32_t a, uint32_t cnt) {
    asm volatile("mbarrier.init.shared.b64 [%0], %1;" :: "r"(a), "r"(cnt) : "memory");
}
// Arrive on a (possibly remote) cluster-mapped mbarrier; release at cluster
// scope orders this thread's prior st.shared::cluster stores.
__device__ __forceinline__ void mbar_arrive_cluster(uint32_t addr) {
    asm volatile("mbarrier.arrive.release.cluster.shared::cluster.b64 _, [%0];"
                 :: "r"(addr) : "memory");
}
__device__ __forceinline__ void mbar_wait_par(uint32_t addr, uint32_t parity) {
    uint32_t done;
    asm volatile(
        "{\n\t.reg .pred p;\n\t"
        "mbarrier.try_wait.parity.acquire.cluster.shared::cta.b64 p, [%1], %2;\n\t"
        "selp.b32 %0, 1, 0, p;\n\t}"
        : "=r"(done) : "r"(addr), "r"(parity) : "memory");
    if (!done) {
        asm volatile(
            "{\n\t.reg .pred P1;\n\t"
            "W_%=:\n\t"
            "mbarrier.try_wait.parity.acquire.cluster.shared::cta.b64 P1, [%0], %1, 0x989680;\n\t"
            "@P1 bra.uni D_%=;\n\t"
            "bra.uni W_%=;\n\t"
            "D_%=:\n\t}"
            :: "r"(addr), "r"(parity) : "memory");
    }
}

// Shared layer row (both items), 16 lanes per row. Lane l reads chunk j*16+l.
// Leader stores results to all 4 CTAs, then arrives on each CTA's mbarrier.
template<int NCH>
__device__ __forceinline__ void shared_layer16(
    const float* __restrict__ W, const float* __restrict__ bias,
    const float* __restrict__ act, int in_off, int out_off,
    int row, int l, const uint32_t* __restrict__ peer,
    const uint32_t* __restrict__ peer_mb)
{
    const float4* __restrict__ w4 = reinterpret_cast<const float4*>(W) + row * (NCH * 16);
    const float4* __restrict__ ua = reinterpret_cast<const float4*>(act + in_off);
    const float4* __restrict__ ub = reinterpret_cast<const float4*>(act + ACT_STRIDE + in_off);
    float4 w[NCH];
#pragma unroll
    for (int j = 0; j < NCH; j++) w[j] = __ldg(w4 + j * 16 + l);
    float4 p = make_float4(0.f, 0.f, 0.f, 0.f);
    float4 q = make_float4(0.f, 0.f, 0.f, 0.f);
#pragma unroll
    for (int j = 0; j < NCH; j++) {
        const float4 u = ua[j * 16 + l];
        const float4 v = ub[j * 16 + l];
        p.x = fmaf(w[j].x, u.x, p.x); p.y = fmaf(w[j].y, u.y, p.y);
        p.z = fmaf(w[j].z, u.z, p.z); p.w = fmaf(w[j].w, u.w, p.w);
        q.x = fmaf(w[j].x, v.x, q.x); q.y = fmaf(w[j].y, v.y, q.y);
        q.z = fmaf(w[j].z, v.z, q.z); q.w = fmaf(w[j].w, v.w, q.w);
    }
    float rp = (p.x + p.y) + (p.z + p.w);
    float rq = (q.x + q.y) + (q.z + q.w);
#pragma unroll
    for (int o = 1; o < 16; o <<= 1) {
        rp += __shfl_xor_sync(0xffffffffu, rp, o);
        rq += __shfl_xor_sync(0xffffffffu, rq, o);
    }
    if (l == 0) {
        const float bs = __ldg(bias + row);
        const float a  = fmaxf(rp + bs, 0.f);
        const float b2 = fmaxf(rq + bs, 0.f);
#pragma unroll
        for (int r = 0; r < 4; r++) {
            st_peer(peer[r] + (uint32_t)(out_off + row) * 4, a);
            st_peer(peer[r] + (uint32_t)(ACT_STRIDE + out_off + row) * 4, b2);
            mbar_arrive_cluster(peer_mb[r]);
        }
    }
}

// Local tail layer row (one item), 8 lanes per row.
template<int NCH>
__device__ __forceinline__ void local_layer8(
    const float* __restrict__ W, const float* __restrict__ bias,
    const float* __restrict__ vin, float* __restrict__ vout,
    int row, int l)
{
    const float4* __restrict__ w4 = reinterpret_cast<const float4*>(W) + row * (NCH * 8);
    const float4* __restrict__ u4 = reinterpret_cast<const float4*>(vin);
    float4 w[NCH];
#pragma unroll
    for (int j = 0; j < NCH; j++) w[j] = __ldg(w4 + j * 8 + l);
    float4 p = make_float4(0.f, 0.f, 0.f, 0.f);
#pragma unroll
    for (int j = 0; j < NCH; j++) {
        const float4 u = u4[j * 8 + l];
        p.x = fmaf(w[j].x, u.x, p.x); p.y = fmaf(w[j].y, u.y, p.y);
        p.z = fmaf(w[j].z, u.z, p.z); p.w = fmaf(w[j].w, u.w, p.w);
    }
    float r = (p.x + p.y) + (p.z + p.w);
#pragma unroll
    for (int o = 1; o < 8; o <<= 1) r += __shfl_xor_sync(0xffffffffu, r, o);
    if (l == 0) vout[row] = fmaxf(r + __ldg(bias + row), 0.f);
}

__global__ __launch_bounds__(1024) __cluster_dims__(4, 1, 1)
void gat_c4mb_kernel(
    const float* __restrict__ x, const int* __restrict__ company_idx,
    const float* __restrict__ W_in,  const float* __restrict__ b_in,
    const float* __restrict__ gat_W, const float* __restrict__ gat_b,
    const float* __restrict__ emb,
    const float* __restrict__ W_fuse, const float* __restrict__ b_fuse,
    const float* __restrict__ W_p1, const float* __restrict__ b_p1,
    const float* __restrict__ W_p2, const float* __restrict__ b_p2,
    const float* __restrict__ W_p3, const float* __restrict__ b_p3,
    const float* __restrict__ W_d1, const float* __restrict__ b_d1,
    const float* __restrict__ W_d2, const float* __restrict__ b_d2,
    const float* __restrict__ W_d3, const float* __restrict__ b_d3,
    float* __restrict__ out)
{
    __shared__ __align__(16) float act[2 * ACT_STRIDE];
    __shared__ __align__(8) uint64_t stage_mb;

    const int tid   = threadIdx.x;
    const int grp16 = tid >> 4;        // 0..63
    const int l16   = tid & 15;
    const int grp8  = tid >> 3;        // 0..127
    const int l8    = tid & 7;
    uint32_t rank;
    asm("mov.u32 %0, %%cluster_ctarank;" : "=r"(rank));
    const int b0   = (blockIdx.x >> 2) * 2;   // 2 items per 4-CTA cluster
    const int base = rank * 64;               // row quarter owned by this CTA

    uint32_t peer[4], peer_mb[4];
    {
        const uint32_t a  = smem_u32(act);
        const uint32_t mb = smem_u32(&stage_mb);
#pragma unroll
        for (int r = 0; r < 4; r++) {
            peer[r]    = mapa_u32(a, r);
            peer_mb[r] = mapa_u32(mb, r);
        }
    }
    const uint32_t my_mb = smem_u32(&stage_mb);

    if (tid == 0) mbar_init(my_mb, 256);   // 64 leaders x 4 CTAs per stage

    // init: x rows + emb rows for both items (each CTA local copy)
    if (tid < 128) {
        const int it = tid >> 6, c = tid & 63;
        const int bb = b0 + it;
        float* s0 = act + it * ACT_STRIDE;
        s0[c]       = __ldg(&x[bb * IN_DIM + c]);
        s0[256 + c] = __ldg(&emb[__ldg(&company_idx[bb]) * IN_DIM + c]);
    }
    __syncthreads();
    cluster_sync();   // publish mbarrier init cluster-wide before any arrive

    // stage 0 — W_in: 256x64, s0[0:64] -> s1
    shared_layer16<1>(W_in, b_in, act, 0, 320, base + grp16, l16, peer, peer_mb);
    mbar_wait_par(my_mb, 0);
    // stage 1..3 — GAT layers (uniform-node collapse): 256x256
    shared_layer16<4>(gat_W,          gat_b,       act, 320, 0,   base + grp16, l16, peer, peer_mb);
    mbar_wait_par(my_mb, 1);
    shared_layer16<4>(gat_W +  65536, gat_b + 256, act, 0,   320, base + grp16, l16, peer, peer_mb);
    mbar_wait_par(my_mb, 0);
    shared_layer16<4>(gat_W + 131072, gat_b + 512, act, 320, 0,   base + grp16, l16, peer, peer_mb);
    mbar_wait_par(my_mb, 1);
    // stage 4 — fuse: 256x320 (s0 = [gat2 | emb]) -> s1
    shared_layer16<5>(W_fuse, b_fuse, act, 0, 320, base + grp16, l16, peer, peer_mb);
    mbar_wait_par(my_mb, 0);

    // tail: rank -> (branch = rank>>1, item = rank&1), fully local from here
    const int item   = rank & 1;
    const int branch = rank >> 1;            // 0 = price, 1 = direction
    const float* W1 = branch ? W_d1 : W_p1;
    const float* c1 = branch ? b_d1 : b_p1;
    const float* W2 = branch ? W_d2 : W_p2;
    const float* c2 = branch ? b_d2 : b_p2;
    const float* W3 = branch ? W_d3 : W_p3;
    const float* c3 = branch ? b_d3 : b_p3;
    const float* fused = act + item * ACT_STRIDE + 320;

    // l1: 128x256, fused -> act[0:128] (scratch; s0 of item0 is dead now)
    local_layer8<8>(W1, c1, fused, act, grp8, l8);
    __syncthreads();
    // l2: 64x128, act[0:128] -> act[576:640]
    if (grp8 < 64)
        local_layer8<4>(W2, c2, act, act + 576, grp8, l8);
    __syncthreads();

    // head: warp 0, 64-dot
    if (tid < 32) {
        const float2 wv = __ldg(&reinterpret_cast<const float2*>(W3)[tid]);
        const float2 vv = reinterpret_cast<const float2*>(act + 576)[tid];
        float r = fmaf(wv.x, vv.x, wv.y * vv.y);
#pragma unroll
        for (int o = 16; o; o >>= 1) r += __shfl_xor_sync(0xffffffffu, r, o);
        if (tid == 0) {
            const float v = r + __ldg(c3);
            const int bb = b0 + item;
            if (branch == 0) out[bb] = v;                            // price
            else             out[64 + bb] = 1.f / (1.f + expf(-v));  // direction
        }
    }
    // last cross-CTA writes were fuse-stage stores, all delivered before the
    // parity-0 wait above completed -> safe to exit without a cluster sync.
}

extern "C" void kernel_launch(void* const* d_in, const int* in_sizes, int n_in,
                              void* d_out, int out_size) {
    const float* x      = (const float*)d_in[0];
    const int*   ci     = (const int*)  d_in[1];
    const float* W_in   = (const float*)d_in[4];
    const float* b_in   = (const float*)d_in[5];
    const float* gat_W  = (const float*)d_in[6];
    const float* gat_b  = (const float*)d_in[11];
    const float* emb    = (const float*)d_in[12];
    const float* W_fuse = (const float*)d_in[13];
    const float* b_fuse = (const float*)d_in[14];
    const float* W_p1   = (const float*)d_in[15];
    const float* b_p1   = (const float*)d_in[16];
    const float* W_p2   = (const float*)d_in[17];
    const float* b_p2   = (const float*)d_in[18];
    const float* W_p3   = (const float*)d_in[19];
    const float* b_p3   = (const float*)d_in[20];
    const float* W_d1   = (const float*)d_in[21];
    const float* b_d1   = (const float*)d_in[22];
    const float* W_d2   = (const float*)d_in[23];
    const float* b_d2   = (const float*)d_in[24];
    const float* W_d3   = (const float*)d_in[25];
    const float* b_d3   = (const float*)d_in[26];

    const int B = in_sizes[0] / IN_DIM;  // 64

    // 32 clusters x 4 CTAs = 128 blocks, 2 items per cluster
    gat_c4mb_kernel<<<B * 2, 1024>>>(
        x, ci, W_in, b_in, gat_W, gat_b, emb, W_fuse, b_fuse,
        W_p1, b_p1, W_p2, b_p2, W_p3, b_p3,
        W_d1, b_d1, W_d2, b_d2, W_d3, b_d3,
        (float*)d_out);
}